// round 4
// baseline (speedup 1.0000x reference)
#include <cuda_runtime.h>

// ---------------------------------------------------------------------------
// PointGiraffeLayer: 3-NN interpolate -> FC(BN,ReLU) -> 3-NN interpolate -> FC
// Shapes (fixed): B=2, N1=8192, N2=4096, N4=2048, C=128
// ---------------------------------------------------------------------------

#define CCH 128

// Scratch (device globals -- no allocation allowed)
__device__ float g_f2i[2 * 4096 * CCH];
__device__ float g_h3 [2 * 4096 * CCH];
__device__ float g_n3 [2 * 4096 * CCH];
__device__ float g_n3i[2 * 8192 * CCH];
__device__ float g_h4 [2 * 8192 * CCH];
__device__ float g_psum[512 * 128];       // per-block column sums (<=512 chunks)
__device__ float g_psq [512 * 128];
__device__ float g_scale[128];
__device__ float g_shift[128];

// ---------------------------------------------------------------------------
// 3-NN interpolation. One warp handles TPW targets; sources cached in smem
// as packed float4 (x,y,z,pad) -> one LDS.128 per source.
// ---------------------------------------------------------------------------
__device__ __forceinline__ void ins3(float d, int s,
                                     float& d0, int& i0,
                                     float& d1, int& i1,
                                     float& d2, int& i2) {
    if (d < d2) {
        if (d < d1) {
            d2 = d1; i2 = i1;
            if (d < d0) { d1 = d0; i1 = i0; d0 = d; i0 = s; }
            else        { d1 = d;  i1 = s; }
        } else { d2 = d; i2 = s; }
    }
}

constexpr int IWARPS = 8;   // warps per block
constexpr int TPW    = 4;   // targets per warp

__global__ void interp3nn(const float* __restrict__ src_xyz,   // (B,NS,3)
                          const float* __restrict__ tgt_xyz,   // (B,NT,3)
                          const float* __restrict__ feats,     // (B*NS,128)
                          float* __restrict__ out,             // (B*NT,128)
                          int NS, int NT) {
    extern __shared__ float4 sp[];   // NS packed xyz

    const int b = blockIdx.y;
    const float* S = src_xyz + (size_t)b * NS * 3;
    for (int i = threadIdx.x; i < NS; i += blockDim.x) {
        float4 p;
        p.x = S[3 * i + 0];
        p.y = S[3 * i + 1];
        p.z = S[3 * i + 2];
        p.w = 0.f;
        sp[i] = p;
    }
    __syncthreads();

    const int warp = threadIdx.x >> 5;
    const int lane = threadIdx.x & 31;
    const int tbase = (blockIdx.x * IWARPS + warp) * TPW;
    if (tbase >= NT) return;

    float tx[TPW], ty[TPW], tz[TPW];
    float d0[TPW], d1[TPW], d2[TPW];
    int   i0[TPW], i1[TPW], i2[TPW];
#pragma unroll
    for (int j = 0; j < TPW; j++) {
        int t = min(tbase + j, NT - 1);
        const float* T = tgt_xyz + ((size_t)b * NT + t) * 3;
        tx[j] = T[0]; ty[j] = T[1]; tz[j] = T[2];
        d0[j] = d1[j] = d2[j] = 3.4e38f;
        i0[j] = i1[j] = i2[j] = 0;
    }

    for (int s = lane; s < NS; s += 32) {
        float4 p = sp[s];
#pragma unroll
        for (int j = 0; j < TPW; j++) {
            float dx = tx[j] - p.x, dy = ty[j] - p.y, dz = tz[j] - p.z;
            float d = dx * dx + dy * dy + dz * dz;
            ins3(d, s, d0[j], i0[j], d1[j], i1[j], d2[j], i2[j]);
        }
    }

    // butterfly merge of sorted triples across the warp
#pragma unroll
    for (int j = 0; j < TPW; j++) {
#pragma unroll
        for (int off = 16; off > 0; off >>= 1) {
            float od0 = __shfl_xor_sync(0xffffffffu, d0[j], off);
            int   oi0 = __shfl_xor_sync(0xffffffffu, i0[j], off);
            float od1 = __shfl_xor_sync(0xffffffffu, d1[j], off);
            int   oi1 = __shfl_xor_sync(0xffffffffu, i1[j], off);
            float od2 = __shfl_xor_sync(0xffffffffu, d2[j], off);
            int   oi2 = __shfl_xor_sync(0xffffffffu, i2[j], off);
            ins3(od0, oi0, d0[j], i0[j], d1[j], i1[j], d2[j], i2[j]);
            ins3(od1, oi1, d0[j], i0[j], d1[j], i1[j], d2[j], i2[j]);
            ins3(od2, oi2, d0[j], i0[j], d1[j], i1[j], d2[j], i2[j]);
        }
    }

    // weights + 3-row gather (float4 per lane: 32 lanes * 4 = 128 channels)
#pragma unroll
    for (int j = 0; j < TPW; j++) {
        int t = tbase + j;
        if (t >= NT) break;
        float s0 = sqrtf(fmaxf(d0[j], 0.f));
        float s1 = sqrtf(fmaxf(d1[j], 0.f));
        float s2 = sqrtf(fmaxf(d2[j], 0.f));
        float w0 = 1.f / (s0 + 1e-8f);
        float w1 = 1.f / (s1 + 1e-8f);
        float w2 = 1.f / (s2 + 1e-8f);
        float wi = 1.f / (w0 + w1 + w2);
        w0 *= wi; w1 *= wi; w2 *= wi;

        const float4* f0 = (const float4*)(feats + ((size_t)b * NS + i0[j]) * CCH);
        const float4* f1 = (const float4*)(feats + ((size_t)b * NS + i1[j]) * CCH);
        const float4* f2 = (const float4*)(feats + ((size_t)b * NS + i2[j]) * CCH);
        float4 a = f0[lane], bb = f1[lane], cc = f2[lane];
        float4 r;
        r.x = w0 * a.x + w1 * bb.x + w2 * cc.x;
        r.y = w0 * a.y + w1 * bb.y + w2 * cc.y;
        r.z = w0 * a.z + w1 * bb.z + w2 * cc.z;
        r.w = w0 * a.w + w1 * bb.w + w2 * cc.w;
        ((float4*)(out + ((size_t)b * NT + t) * CCH))[lane] = r;
    }
}

// ---------------------------------------------------------------------------
// Tiled SGEMM: C (N x 128) = X (N x KD) @ W^T  (W is (128, KD) row-major)
// Tile 32(M) x 128(N) x 16(K), 128 threads, 4x8 microtile -> grid = N/32
// SPLIT : X = concat(A0, A1) along K (each N x 128)
// AFFINE: x -> relu(x * scale[k] + shift[k]) applied on load (BN+ReLU fusion)
// SUMS  : emit per-block column sum / sumsq of C (pre-bias) -> BN stats
// BIAS  : add bias[col] at epilogue
// ---------------------------------------------------------------------------
template <int KD, bool SPLIT, bool AFFINE, bool SUMS, bool BIAS>
__global__ __launch_bounds__(128) void gemm128(
        const float* __restrict__ A0, const float* __restrict__ A1,
        const float* __restrict__ W,
        const float* __restrict__ scale, const float* __restrict__ shift,
        const float* __restrict__ bias,
        float* __restrict__ Cout,
        float* __restrict__ psum, float* __restrict__ psq) {
    __shared__ float As[16][32];
    __shared__ float Bs[16][128];

    const int t  = threadIdx.x;
    const int tx = t & 15;        // 16 col groups (x8 = 128 cols)
    const int ty = t >> 4;        // 8 row groups  (x4 = 32 rows)
    const int blockRow = blockIdx.x * 32;

    float acc[4][8];
#pragma unroll
    for (int i = 0; i < 4; i++)
#pragma unroll
        for (int j = 0; j < 8; j++) acc[i][j] = 0.f;

    for (int k0 = 0; k0 < KD; k0 += 16) {
        // --- load A tile (32 rows x 16 k) = 128 float4 slots, 1 per thread ---
        {
            int row = t >> 2;
            int kq  = (t & 3) << 2;
            int kg  = k0 + kq;
            const float* src;
            if (SPLIT) {
                src = (kg < 128) ? (A0 + (size_t)(blockRow + row) * 128 + kg)
                                 : (A1 + (size_t)(blockRow + row) * 128 + (kg - 128));
            } else {
                src = A0 + (size_t)(blockRow + row) * KD + kg;
            }
            float4 v = *(const float4*)src;
            if (AFFINE) {
                v.x = fmaxf(v.x * scale[kg + 0] + shift[kg + 0], 0.f);
                v.y = fmaxf(v.y * scale[kg + 1] + shift[kg + 1], 0.f);
                v.z = fmaxf(v.z * scale[kg + 2] + shift[kg + 2], 0.f);
                v.w = fmaxf(v.w * scale[kg + 3] + shift[kg + 3], 0.f);
            }
            As[kq + 0][row] = v.x;
            As[kq + 1][row] = v.y;
            As[kq + 2][row] = v.z;
            As[kq + 3][row] = v.w;
        }
        // --- load B tile (W^T, 128 oc x 16 k) = 512 float4 slots, 4/thread ---
#pragma unroll
        for (int i = 0; i < 4; i++) {
            int f  = t + i * 128;
            int oc = f >> 2;
            int kq = (f & 3) << 2;
            float4 v = *(const float4*)(W + (size_t)oc * KD + k0 + kq);
            Bs[kq + 0][oc] = v.x;
            Bs[kq + 1][oc] = v.y;
            Bs[kq + 2][oc] = v.z;
            Bs[kq + 3][oc] = v.w;
        }
        __syncthreads();

#pragma unroll
        for (int k = 0; k < 16; k++) {
            float4 a  = *(const float4*)&As[k][ty * 4];
            float4 b0 = *(const float4*)&Bs[k][tx * 8];
            float4 b1 = *(const float4*)&Bs[k][tx * 8 + 4];
            float ar[4] = {a.x, a.y, a.z, a.w};
            float br[8] = {b0.x, b0.y, b0.z, b0.w, b1.x, b1.y, b1.z, b1.w};
#pragma unroll
            for (int i = 0; i < 4; i++)
#pragma unroll
                for (int j = 0; j < 8; j++) acc[i][j] += ar[i] * br[j];
        }
        __syncthreads();
    }

    // --- epilogue: store ---
    const int r0 = blockRow + ty * 4;
    const int c0 = tx * 8;
#pragma unroll
    for (int i = 0; i < 4; i++) {
        float4 v0, v1;
        v0.x = acc[i][0]; v0.y = acc[i][1]; v0.z = acc[i][2]; v0.w = acc[i][3];
        v1.x = acc[i][4]; v1.y = acc[i][5]; v1.z = acc[i][6]; v1.w = acc[i][7];
        if (BIAS) {
            v0.x += bias[c0 + 0]; v0.y += bias[c0 + 1]; v0.z += bias[c0 + 2]; v0.w += bias[c0 + 3];
            v1.x += bias[c0 + 4]; v1.y += bias[c0 + 5]; v1.z += bias[c0 + 6]; v1.w += bias[c0 + 7];
        }
        *(float4*)(Cout + (size_t)(r0 + i) * 128 + c0)     = v0;
        *(float4*)(Cout + (size_t)(r0 + i) * 128 + c0 + 4) = v1;
    }

    // --- deterministic per-block BN partials (pre-bias values) ---
    if (SUMS) {
        float cs[8], cq[8];
#pragma unroll
        for (int j = 0; j < 8; j++) {
            float s = 0.f, q = 0.f;
#pragma unroll
            for (int i = 0; i < 4; i++) { s += acc[i][j]; q += acc[i][j] * acc[i][j]; }
            cs[j] = s; cq[j] = q;
        }
        float* red = &Bs[0][0];   // reuse Bs: need 8*128 = 1024 floats (Bs has 2048)
        __syncthreads();
#pragma unroll
        for (int j = 0; j < 8; j++) red[ty * 128 + c0 + j] = cs[j];
        __syncthreads();
        {
            float s = 0.f;
#pragma unroll
            for (int y = 0; y < 8; y++) s += red[y * 128 + t];
            psum[blockIdx.x * 128 + t] = s;
        }
        __syncthreads();
#pragma unroll
        for (int j = 0; j < 8; j++) red[ty * 128 + c0 + j] = cq[j];
        __syncthreads();
        {
            float s = 0.f;
#pragma unroll
            for (int y = 0; y < 8; y++) s += red[y * 128 + t];
            psq[blockIdx.x * 128 + t] = s;
        }
    }
}

// ---------------------------------------------------------------------------
// BN finalize (parallel): 1024 threads = 128 channels x 8 slices.
// Each slice sums nchunks/8 strided entries; smem tree combines.
// ---------------------------------------------------------------------------
__global__ __launch_bounds__(1024) void bn_finalize(
        const float* __restrict__ psum, const float* __restrict__ psq,
        int nchunks, float invN,
        const float* __restrict__ g, const float* __restrict__ b,
        float* __restrict__ scale, float* __restrict__ shift) {
    __shared__ float ssum[8][128];
    __shared__ float ssq [8][128];
    const int c     = threadIdx.x & 127;
    const int slice = threadIdx.x >> 7;   // 0..7

    float s = 0.f, q = 0.f;
    for (int k = slice; k < nchunks; k += 32) {   // 4-deep MLP per slice
        float s0 = psum[(k     ) * 128 + c];
        float q0 = psq [(k     ) * 128 + c];
        float s1 = (k +  8 < nchunks) ? psum[(k +  8) * 128 + c] : 0.f;
        float q1 = (k +  8 < nchunks) ? psq [(k +  8) * 128 + c] : 0.f;
        float s2 = (k + 16 < nchunks) ? psum[(k + 16) * 128 + c] : 0.f;
        float q2 = (k + 16 < nchunks) ? psq [(k + 16) * 128 + c] : 0.f;
        float s3 = (k + 24 < nchunks) ? psum[(k + 24) * 128 + c] : 0.f;
        float q3 = (k + 24 < nchunks) ? psq [(k + 24) * 128 + c] : 0.f;
        s += (s0 + s1) + (s2 + s3);
        q += (q0 + q1) + (q2 + q3);
    }
    ssum[slice][c] = s;
    ssq [slice][c] = q;
    __syncthreads();

    if (threadIdx.x < 128) {
        float ts = 0.f, tq = 0.f;
#pragma unroll
        for (int y = 0; y < 8; y++) { ts += ssum[y][c]; tq += ssq[y][c]; }
        float mu  = ts * invN;
        float var = fmaxf(tq * invN - mu * mu, 0.f);
        float sc  = g[c] * rsqrtf(var + 1e-5f);
        scale[c] = sc;
        shift[c] = b[c] - mu * sc;
    }
}

// ---------------------------------------------------------------------------
// Launch
// ---------------------------------------------------------------------------
extern "C" void kernel_launch(void* const* d_in, const int* in_sizes, int n_in,
                              void* d_out, int out_size) {
    const float* pts_r1 = (const float*)d_in[0];
    const float* pts_r2 = (const float*)d_in[1];
    const float* pts_r4 = (const float*)d_in[2];
    const float* feat0  = (const float*)d_in[3];
    const float* feat1  = (const float*)d_in[4];
    const float* feat2  = (const float*)d_in[5];
    const float* w3a = (const float*)d_in[6];
    const float* g3  = (const float*)d_in[7];
    const float* b3  = (const float*)d_in[8];
    const float* w3b = (const float*)d_in[9];
    const float* bb3 = (const float*)d_in[10];
    const float* w4a = (const float*)d_in[11];
    const float* g4  = (const float*)d_in[12];
    const float* b4  = (const float*)d_in[13];
    const float* w4b = (const float*)d_in[14];
    const float* bb4 = (const float*)d_in[15];

    const int B  = 2;
    const int N1 = in_sizes[0] / (3 * B);   // 8192
    const int N2 = in_sizes[1] / (3 * B);   // 4096
    const int N4 = in_sizes[2] / (3 * B);   // 2048

    float *f2i, *h3, *n3, *n3i, *h4, *psum, *psq, *scale, *shift;
    cudaGetSymbolAddress((void**)&f2i,   g_f2i);
    cudaGetSymbolAddress((void**)&h3,    g_h3);
    cudaGetSymbolAddress((void**)&n3,    g_n3);
    cudaGetSymbolAddress((void**)&n3i,   g_n3i);
    cudaGetSymbolAddress((void**)&h4,    g_h4);
    cudaGetSymbolAddress((void**)&psum,  g_psum);
    cudaGetSymbolAddress((void**)&psq,   g_psq);
    cudaGetSymbolAddress((void**)&scale, g_scale);
    cudaGetSymbolAddress((void**)&shift, g_shift);

    // allow >48KB dynamic smem for the 4096-source interp (64KB)
    cudaFuncSetAttribute(interp3nn, cudaFuncAttributeMaxDynamicSharedMemorySize,
                         (int)(4096 * sizeof(float4)));

    // --- fnode 3: interp feat2 (r4 grid) onto r2 grid ---
    {
        dim3 grid((N2 + IWARPS * TPW - 1) / (IWARPS * TPW), B);
        size_t shmem = (size_t)N4 * sizeof(float4);
        interp3nn<<<grid, 256, shmem>>>(pts_r4, pts_r2, feat2, f2i, N4, N2);
    }
    // h3 = concat(feat1, f2i) @ w3a^T   (+ BN partial sums)
    gemm128<256, true, false, true, false><<<(B * N2) / 32, 128>>>(
        feat1, f2i, w3a, nullptr, nullptr, nullptr, h3, psum, psq);
    bn_finalize<<<1, 1024>>>(psum, psq, (B * N2) / 32, 1.f / (B * N2), g3, b3, scale, shift);
    // n3 = relu(BN(h3)) @ w3b^T + bb3
    gemm128<128, false, true, false, true><<<(B * N2) / 32, 128>>>(
        h3, nullptr, w3b, scale, shift, bb3, n3, nullptr, nullptr);

    // --- fnode 4: interp n3 (r2 grid) onto r1 grid ---
    {
        dim3 grid((N1 + IWARPS * TPW - 1) / (IWARPS * TPW), B);
        size_t shmem = (size_t)N2 * sizeof(float4);
        interp3nn<<<grid, 256, shmem>>>(pts_r2, pts_r1, n3, n3i, N2, N1);
    }
    // h4 = concat(feat0, n3i) @ w4a^T   (+ BN partial sums)
    gemm128<256, true, false, true, false><<<(B * N1) / 32, 128>>>(
        feat0, n3i, w4a, nullptr, nullptr, nullptr, h4, psum, psq);
    bn_finalize<<<1, 1024>>>(psum, psq, (B * N1) / 32, 1.f / (B * N1), g4, b4, scale, shift);
    // out = relu(BN(h4)) @ w4b^T + bb4
    gemm128<128, false, true, false, true><<<(B * N1) / 32, 128>>>(
        h4, nullptr, w4b, scale, shift, bb4, (float*)d_out, nullptr, nullptr);
}

// round 6
// speedup vs baseline: 1.3860x; 1.3860x over previous
#include <cuda_runtime.h>
#include <cstdint>

// ---------------------------------------------------------------------------
// PointGiraffeLayer: 3-NN interpolate -> FC(BN,ReLU) -> 3-NN interpolate -> FC
// B=2, N1=8192, N2=4096, N4=2048, C=128.
// GEMMs: mma.sync m16n8k8 tf32 with 3xTF32 error compensation.
// ---------------------------------------------------------------------------

#define CCH 128

// Scratch (device globals -- no allocation allowed)
__device__ float g_f2i[2 * 4096 * CCH];
__device__ float g_h3 [2 * 4096 * CCH];
__device__ float g_n3 [2 * 4096 * CCH];
__device__ float g_n3i[2 * 8192 * CCH];
__device__ float g_h4 [2 * 8192 * CCH];
__device__ float g_psum[512 * 128];
__device__ float g_psq [512 * 128];
__device__ float g_scale[128];
__device__ float g_shift[128];

// tf32 round-to-nearest (returns tf32 bit pattern in a u32)
__device__ __forceinline__ uint32_t tf32_rna(float a) {
    uint32_t u;
    asm("cvt.rna.tf32.f32 %0, %1;" : "=r"(u) : "f"(a));
    return u;
}

__device__ __forceinline__ void mma_tf32(float c[4], const uint32_t a[4],
                                         const uint32_t b[2]) {
    asm volatile(
        "mma.sync.aligned.m16n8k8.row.col.f32.tf32.tf32.f32 "
        "{%0,%1,%2,%3}, {%4,%5,%6,%7}, {%8,%9}, {%0,%1,%2,%3};"
        : "+f"(c[0]), "+f"(c[1]), "+f"(c[2]), "+f"(c[3])
        : "r"(a[0]), "r"(a[1]), "r"(a[2]), "r"(a[3]), "r"(b[0]), "r"(b[1]));
}

// ---------------------------------------------------------------------------
// 3-NN interpolation (unchanged)
// ---------------------------------------------------------------------------
__device__ __forceinline__ void ins3(float d, int s,
                                     float& d0, int& i0,
                                     float& d1, int& i1,
                                     float& d2, int& i2) {
    if (d < d2) {
        if (d < d1) {
            d2 = d1; i2 = i1;
            if (d < d0) { d1 = d0; i1 = i0; d0 = d; i0 = s; }
            else        { d1 = d;  i1 = s; }
        } else { d2 = d; i2 = s; }
    }
}

constexpr int IWARPS = 8;
constexpr int TPW    = 4;

__global__ void interp3nn(const float* __restrict__ src_xyz,
                          const float* __restrict__ tgt_xyz,
                          const float* __restrict__ feats,
                          float* __restrict__ out,
                          int NS, int NT) {
    extern __shared__ float4 sp[];

    const int b = blockIdx.y;
    const float* S = src_xyz + (size_t)b * NS * 3;
    for (int i = threadIdx.x; i < NS; i += blockDim.x) {
        float4 p;
        p.x = S[3 * i + 0];
        p.y = S[3 * i + 1];
        p.z = S[3 * i + 2];
        p.w = 0.f;
        sp[i] = p;
    }
    __syncthreads();

    const int warp = threadIdx.x >> 5;
    const int lane = threadIdx.x & 31;
    const int tbase = (blockIdx.x * IWARPS + warp) * TPW;
    if (tbase >= NT) return;

    float tx[TPW], ty[TPW], tz[TPW];
    float d0[TPW], d1[TPW], d2[TPW];
    int   i0[TPW], i1[TPW], i2[TPW];
#pragma unroll
    for (int j = 0; j < TPW; j++) {
        int t = min(tbase + j, NT - 1);
        const float* T = tgt_xyz + ((size_t)b * NT + t) * 3;
        tx[j] = T[0]; ty[j] = T[1]; tz[j] = T[2];
        d0[j] = d1[j] = d2[j] = 3.4e38f;
        i0[j] = i1[j] = i2[j] = 0;
    }

    for (int s = lane; s < NS; s += 32) {
        float4 p = sp[s];
#pragma unroll
        for (int j = 0; j < TPW; j++) {
            float dx = tx[j] - p.x, dy = ty[j] - p.y, dz = tz[j] - p.z;
            float d = dx * dx + dy * dy + dz * dz;
            ins3(d, s, d0[j], i0[j], d1[j], i1[j], d2[j], i2[j]);
        }
    }

#pragma unroll
    for (int j = 0; j < TPW; j++) {
#pragma unroll
        for (int off = 16; off > 0; off >>= 1) {
            float od0 = __shfl_xor_sync(0xffffffffu, d0[j], off);
            int   oi0 = __shfl_xor_sync(0xffffffffu, i0[j], off);
            float od1 = __shfl_xor_sync(0xffffffffu, d1[j], off);
            int   oi1 = __shfl_xor_sync(0xffffffffu, i1[j], off);
            float od2 = __shfl_xor_sync(0xffffffffu, d2[j], off);
            int   oi2 = __shfl_xor_sync(0xffffffffu, i2[j], off);
            ins3(od0, oi0, d0[j], i0[j], d1[j], i1[j], d2[j], i2[j]);
            ins3(od1, oi1, d0[j], i0[j], d1[j], i1[j], d2[j], i2[j]);
            ins3(od2, oi2, d0[j], i0[j], d1[j], i1[j], d2[j], i2[j]);
        }
    }

#pragma unroll
    for (int j = 0; j < TPW; j++) {
        int t = tbase + j;
        if (t >= NT) break;
        float s0 = sqrtf(fmaxf(d0[j], 0.f));
        float s1 = sqrtf(fmaxf(d1[j], 0.f));
        float s2 = sqrtf(fmaxf(d2[j], 0.f));
        float w0 = 1.f / (s0 + 1e-8f);
        float w1 = 1.f / (s1 + 1e-8f);
        float w2 = 1.f / (s2 + 1e-8f);
        float wi = 1.f / (w0 + w1 + w2);
        w0 *= wi; w1 *= wi; w2 *= wi;

        const float4* f0 = (const float4*)(feats + ((size_t)b * NS + i0[j]) * CCH);
        const float4* f1 = (const float4*)(feats + ((size_t)b * NS + i1[j]) * CCH);
        const float4* f2 = (const float4*)(feats + ((size_t)b * NS + i2[j]) * CCH);
        float4 a = f0[lane], bb = f1[lane], cc = f2[lane];
        float4 r;
        r.x = w0 * a.x + w1 * bb.x + w2 * cc.x;
        r.y = w0 * a.y + w1 * bb.y + w2 * cc.y;
        r.z = w0 * a.z + w1 * bb.z + w2 * cc.z;
        r.w = w0 * a.w + w1 * bb.w + w2 * cc.w;
        ((float4*)(out + ((size_t)b * NT + t) * CCH))[lane] = r;
    }
}

// ---------------------------------------------------------------------------
// mma.sync tf32 GEMM (3xTF32 compensated):
//   C (rows x 128) = X (rows x KD) @ W^T,  W (128, KD) row-major.
// CTA tile: 128(M) x 64(N) x 32(K). 256 threads = 8 warps (4x2).
// grid = (rows/128, 2): blockIdx.y selects the 64-col half of W.
// SPLIT: X = concat(A0,A1) on K. AFFINE: relu(x*scale+shift) on A load.
// SUMS: per-block column sum/sumsq (pre-bias). BIAS: +bias at store.
// ---------------------------------------------------------------------------
constexpr int SA = 36;   // padded smem stride (words) -> conflict-free frags
constexpr int SC = 68;   // stage stride

template <int KD, bool SPLIT, bool AFFINE, bool SUMS, bool BIAS>
__global__ __launch_bounds__(256) void gemm_mma(
        const float* __restrict__ A0, const float* __restrict__ A1,
        const float* __restrict__ W,
        const float* __restrict__ scale, const float* __restrict__ shift,
        const float* __restrict__ bias,
        float* __restrict__ Cout,
        float* __restrict__ psum, float* __restrict__ psq) {
    extern __shared__ float smf[];
    uint32_t* As_hi = (uint32_t*)smf;             // 128*SA
    uint32_t* As_lo = As_hi + 128 * SA;
    uint32_t* Bs_hi = As_lo + 128 * SA;           // 64*SA
    uint32_t* Bs_lo = Bs_hi + 64 * SA;

    const int t    = threadIdx.x;
    const int lane = t & 31;
    const int warp = t >> 5;
    const int wm   = warp >> 1;          // 0..3
    const int wn   = warp & 1;           // 0..1
    const int g    = lane >> 2;          // 0..7
    const int tig  = lane & 3;           // 0..3
    const int blockRow = blockIdx.x * 128;
    const int oc0      = blockIdx.y * 64;

    float c[2][4][4];
#pragma unroll
    for (int am = 0; am < 2; am++)
#pragma unroll
        for (int bn = 0; bn < 4; bn++)
#pragma unroll
            for (int r = 0; r < 4; r++) c[am][bn][r] = 0.f;

    constexpr int CHUNKS = KD / 32;
    for (int kc = 0; kc < CHUNKS; kc++) {
        __syncthreads();   // previous chunk's frags fully consumed

        // ---- A chunk: 128 rows x 32 k = 1024 float4, 4 per thread ----
#pragma unroll
        for (int i = 0; i < 4; i++) {
            int idx = t + i * 256;
            int row = idx >> 3;
            int cq  = (idx & 7) * 4;
            int kg  = kc * 32 + cq;
            const float* src;
            if (SPLIT) {
                src = (kg < 128) ? A0 + (size_t)(blockRow + row) * 128 + kg
                                 : A1 + (size_t)(blockRow + row) * 128 + (kg - 128);
            } else {
                src = A0 + (size_t)(blockRow + row) * KD + kg;
            }
            float4 v = *(const float4*)src;
            if (AFFINE) {
                v.x = fmaxf(v.x * scale[kg + 0] + shift[kg + 0], 0.f);
                v.y = fmaxf(v.y * scale[kg + 1] + shift[kg + 1], 0.f);
                v.z = fmaxf(v.z * scale[kg + 2] + shift[kg + 2], 0.f);
                v.w = fmaxf(v.w * scale[kg + 3] + shift[kg + 3], 0.f);
            }
            float vv[4] = {v.x, v.y, v.z, v.w};
#pragma unroll
            for (int j = 0; j < 4; j++) {
                uint32_t hi = tf32_rna(vv[j]);
                float lo = vv[j] - __uint_as_float(hi);
                As_hi[row * SA + cq + j] = hi;
                As_lo[row * SA + cq + j] = __float_as_uint(lo);
            }
        }
        // ---- B chunk: 64 oc x 32 k = 512 float4, 2 per thread ----
#pragma unroll
        for (int i = 0; i < 2; i++) {
            int idx = t + i * 256;
            int row = idx >> 3;
            int cq  = (idx & 7) * 4;
            float4 v = *(const float4*)(W + (size_t)(oc0 + row) * KD + kc * 32 + cq);
            float vv[4] = {v.x, v.y, v.z, v.w};
#pragma unroll
            for (int j = 0; j < 4; j++) {
                uint32_t hi = tf32_rna(vv[j]);
                float lo = vv[j] - __uint_as_float(hi);
                Bs_hi[row * SA + cq + j] = hi;
                Bs_lo[row * SA + cq + j] = __float_as_uint(lo);
            }
        }
        __syncthreads();

        // ---- 4 k8 steps ----
#pragma unroll
        for (int ks = 0; ks < 4; ks++) {
            int k0 = ks * 8;
            uint32_t ah[2][4], al[2][4];
#pragma unroll
            for (int am = 0; am < 2; am++) {
                int r = wm * 32 + am * 16 + g;
                ah[am][0] = As_hi[(r    ) * SA + k0 + tig];
                ah[am][1] = As_hi[(r + 8) * SA + k0 + tig];
                ah[am][2] = As_hi[(r    ) * SA + k0 + tig + 4];
                ah[am][3] = As_hi[(r + 8) * SA + k0 + tig + 4];
                al[am][0] = As_lo[(r    ) * SA + k0 + tig];
                al[am][1] = As_lo[(r + 8) * SA + k0 + tig];
                al[am][2] = As_lo[(r    ) * SA + k0 + tig + 4];
                al[am][3] = As_lo[(r + 8) * SA + k0 + tig + 4];
            }
            uint32_t bh[4][2], bl[4][2];
#pragma unroll
            for (int bn = 0; bn < 4; bn++) {
                int n = wn * 32 + bn * 8 + g;
                bh[bn][0] = Bs_hi[n * SA + k0 + tig];
                bh[bn][1] = Bs_hi[n * SA + k0 + tig + 4];
                bl[bn][0] = Bs_lo[n * SA + k0 + tig];
                bl[bn][1] = Bs_lo[n * SA + k0 + tig + 4];
            }
#pragma unroll
            for (int am = 0; am < 2; am++)
#pragma unroll
                for (int bn = 0; bn < 4; bn++) {
                    mma_tf32(c[am][bn], ah[am], bh[bn]);
                    mma_tf32(c[am][bn], ah[am], bl[bn]);
                    mma_tf32(c[am][bn], al[am], bh[bn]);
                }
        }
    }

    // ---- epilogue: frags -> smem stage (pre-bias) ----
    __syncthreads();
    float* stage = smf;   // 128 x SC, reuses operand smem
#pragma unroll
    for (int am = 0; am < 2; am++) {
        int row0 = wm * 32 + am * 16 + g;
#pragma unroll
        for (int bn = 0; bn < 4; bn++) {
            int col = wn * 32 + bn * 8 + 2 * tig;
            stage[(row0    ) * SC + col    ] = c[am][bn][0];
            stage[(row0    ) * SC + col + 1] = c[am][bn][1];
            stage[(row0 + 8) * SC + col    ] = c[am][bn][2];
            stage[(row0 + 8) * SC + col + 1] = c[am][bn][3];
        }
    }
    __syncthreads();

    if (SUMS && t < 64) {
        float s = 0.f, q = 0.f;
#pragma unroll 8
        for (int r = 0; r < 128; r++) {
            float v = stage[r * SC + t];
            s += v; q += v * v;
        }
        psum[blockIdx.x * 128 + oc0 + t] = s;
        psq [blockIdx.x * 128 + oc0 + t] = q;
    }

    // coalesced store: 128 rows x 16 float4 = 2048 slots, 8 per thread
#pragma unroll
    for (int i = 0; i < 8; i++) {
        int idx = t + i * 256;
        int row = idx >> 4;
        int cq  = (idx & 15) * 4;
        float4 v = *(float4*)&stage[row * SC + cq];
        if (BIAS) {
            v.x += bias[oc0 + cq + 0];
            v.y += bias[oc0 + cq + 1];
            v.z += bias[oc0 + cq + 2];
            v.w += bias[oc0 + cq + 3];
        }
        *(float4*)(Cout + (size_t)(blockRow + row) * 128 + oc0 + cq) = v;
    }
}

constexpr int GEMM_SMEM = (128 * SA * 2 + 64 * SA * 2) * 4;   // 55296 B

// ---------------------------------------------------------------------------
// BN finalize (parallel)
// ---------------------------------------------------------------------------
__global__ __launch_bounds__(1024) void bn_finalize(
        const float* __restrict__ psum, const float* __restrict__ psq,
        int nchunks, float invN,
        const float* __restrict__ g, const float* __restrict__ b,
        float* __restrict__ scale, float* __restrict__ shift) {
    __shared__ float ssum[8][128];
    __shared__ float ssq [8][128];
    const int c     = threadIdx.x & 127;
    const int slice = threadIdx.x >> 7;

    float s = 0.f, q = 0.f;
    for (int k = slice; k < nchunks; k += 8) {
        s += psum[k * 128 + c];
        q += psq [k * 128 + c];
    }
    ssum[slice][c] = s;
    ssq [slice][c] = q;
    __syncthreads();

    if (threadIdx.x < 128) {
        float ts = 0.f, tq = 0.f;
#pragma unroll
        for (int y = 0; y < 8; y++) { ts += ssum[y][c]; tq += ssq[y][c]; }
        float mu  = ts * invN;
        float var = fmaxf(tq * invN - mu * mu, 0.f);
        float sc  = g[c] * rsqrtf(var + 1e-5f);
        scale[c] = sc;
        shift[c] = b[c] - mu * sc;
    }
}

// ---------------------------------------------------------------------------
// Launch
// ---------------------------------------------------------------------------
extern "C" void kernel_launch(void* const* d_in, const int* in_sizes, int n_in,
                              void* d_out, int out_size) {
    const float* pts_r1 = (const float*)d_in[0];
    const float* pts_r2 = (const float*)d_in[1];
    const float* pts_r4 = (const float*)d_in[2];
    const float* feat0  = (const float*)d_in[3];
    const float* feat1  = (const float*)d_in[4];
    const float* feat2  = (const float*)d_in[5];
    const float* w3a = (const float*)d_in[6];
    const float* g3  = (const float*)d_in[7];
    const float* b3  = (const float*)d_in[8];
    const float* w3b = (const float*)d_in[9];
    const float* bb3 = (const float*)d_in[10];
    const float* w4a = (const float*)d_in[11];
    const float* g4  = (const float*)d_in[12];
    const float* b4  = (const float*)d_in[13];
    const float* w4b = (const float*)d_in[14];
    const float* bb4 = (const float*)d_in[15];

    const int B  = 2;
    const int N1 = in_sizes[0] / (3 * B);   // 8192
    const int N2 = in_sizes[1] / (3 * B);   // 4096
    const int N4 = in_sizes[2] / (3 * B);   // 2048

    float *f2i, *h3, *n3, *n3i, *h4, *psum, *psq, *scale, *shift;
    cudaGetSymbolAddress((void**)&f2i,   g_f2i);
    cudaGetSymbolAddress((void**)&h3,    g_h3);
    cudaGetSymbolAddress((void**)&n3,    g_n3);
    cudaGetSymbolAddress((void**)&n3i,   g_n3i);
    cudaGetSymbolAddress((void**)&h4,    g_h4);
    cudaGetSymbolAddress((void**)&psum,  g_psum);
    cudaGetSymbolAddress((void**)&psq,   g_psq);
    cudaGetSymbolAddress((void**)&scale, g_scale);
    cudaGetSymbolAddress((void**)&shift, g_shift);

    cudaFuncSetAttribute(interp3nn, cudaFuncAttributeMaxDynamicSharedMemorySize,
                         (int)(4096 * sizeof(float4)));
    cudaFuncSetAttribute(gemm_mma<256, true, false, true, false>,
                         cudaFuncAttributeMaxDynamicSharedMemorySize, GEMM_SMEM);
    cudaFuncSetAttribute(gemm_mma<128, false, true, false, true>,
                         cudaFuncAttributeMaxDynamicSharedMemorySize, GEMM_SMEM);

    // --- fnode 3: interp feat2 (r4 grid) onto r2 grid ---
    {
        dim3 grid((N2 + IWARPS * TPW - 1) / (IWARPS * TPW), B);
        size_t shmem = (size_t)N4 * sizeof(float4);
        interp3nn<<<grid, 256, shmem>>>(pts_r4, pts_r2, feat2, f2i, N4, N2);
    }
    // h3 = concat(feat1, f2i) @ w3a^T (+ BN partial sums)
    gemm_mma<256, true, false, true, false>
        <<<dim3((B * N2) / 128, 2), 256, GEMM_SMEM>>>(
        feat1, f2i, w3a, nullptr, nullptr, nullptr, h3, psum, psq);
    bn_finalize<<<1, 1024>>>(psum, psq, (B * N2) / 128, 1.f / (B * N2), g3, b3, scale, shift);
    // n3 = relu(BN(h3)) @ w3b^T + bb3
    gemm_mma<128, false, true, false, true>
        <<<dim3((B * N2) / 128, 2), 256, GEMM_SMEM>>>(
        h3, nullptr, w3b, scale, shift, bb3, n3, nullptr, nullptr);

    // --- fnode 4: interp n3 (r2 grid) onto r1 grid ---
    {
        dim3 grid((N1 + IWARPS * TPW - 1) / (IWARPS * TPW), B);
        size_t shmem = (size_t)N2 * sizeof(float4);
        interp3nn<<<grid, 256, shmem>>>(pts_r2, pts_r1, n3, n3i, N2, N1);
    }
    // h4 = concat(feat0, n3i) @ w4a^T (+ BN partial sums)
    gemm_mma<256, true, false, true, false>
        <<<dim3((B * N1) / 128, 2), 256, GEMM_SMEM>>>(
        feat0, n3i, w4a, nullptr, nullptr, nullptr, h4, psum, psq);
    bn_finalize<<<1, 1024>>>(psum, psq, (B * N1) / 128, 1.f / (B * N1), g4, b4, scale, shift);
    // out = relu(BN(h4)) @ w4b^T + bb4
    gemm_mma<128, false, true, false, true>
        <<<dim3((B * N1) / 128, 2), 256, GEMM_SMEM>>>(
        h4, nullptr, w4b, scale, shift, bb4, (float*)d_out, nullptr, nullptr);
}

// round 7
// speedup vs baseline: 1.4845x; 1.0711x over previous
#include <cuda_runtime.h>
#include <cstdint>

// ---------------------------------------------------------------------------
// PointGiraffeLayer: 3-NN interpolate -> FC(BN,ReLU) -> 3-NN interpolate -> FC
// B=2, N1=8192, N2=4096, N4=2048, C=128.
// GEMMs: mma.sync m16n8k8 tf32, 3xTF32 compensation, cp.async double buffer.
// ---------------------------------------------------------------------------

#define CCH 128

__device__ float g_f2i[2 * 4096 * CCH];
__device__ float g_h3 [2 * 4096 * CCH];
__device__ float g_n3 [2 * 4096 * CCH];
__device__ float g_n3i[2 * 8192 * CCH];
__device__ float g_h4 [2 * 8192 * CCH];
__device__ float g_psum[512 * 128];
__device__ float g_psq [512 * 128];
__device__ float g_scale[128];
__device__ float g_shift[128];

__device__ __forceinline__ uint32_t tf32_rna(float a) {
    uint32_t u;
    asm("cvt.rna.tf32.f32 %0, %1;" : "=r"(u) : "f"(a));
    return u;
}

__device__ __forceinline__ void mma_tf32(float c[4], const uint32_t a[4],
                                         const uint32_t b[2]) {
    asm volatile(
        "mma.sync.aligned.m16n8k8.row.col.f32.tf32.tf32.f32 "
        "{%0,%1,%2,%3}, {%4,%5,%6,%7}, {%8,%9}, {%0,%1,%2,%3};"
        : "+f"(c[0]), "+f"(c[1]), "+f"(c[2]), "+f"(c[3])
        : "r"(a[0]), "r"(a[1]), "r"(a[2]), "r"(a[3]), "r"(b[0]), "r"(b[1]));
}

__device__ __forceinline__ uint32_t smem_u32(const void* p) {
    uint32_t a;
    asm("{ .reg .u64 t; cvta.to.shared.u64 t, %1; cvt.u32.u64 %0, t; }"
        : "=r"(a) : "l"(p));
    return a;
}
__device__ __forceinline__ void cp_async16(uint32_t saddr, const void* g) {
    asm volatile("cp.async.ca.shared.global [%0], [%1], 16;" :: "r"(saddr), "l"(g));
}
__device__ __forceinline__ void cp_commit() {
    asm volatile("cp.async.commit_group;" ::: "memory");
}
template <int N>
__device__ __forceinline__ void cp_wait() {
    asm volatile("cp.async.wait_group %0;" :: "n"(N) : "memory");
}

// ---------------------------------------------------------------------------
// 3-NN interpolation (unchanged)
// ---------------------------------------------------------------------------
__device__ __forceinline__ void ins3(float d, int s,
                                     float& d0, int& i0,
                                     float& d1, int& i1,
                                     float& d2, int& i2) {
    if (d < d2) {
        if (d < d1) {
            d2 = d1; i2 = i1;
            if (d < d0) { d1 = d0; i1 = i0; d0 = d; i0 = s; }
            else        { d1 = d;  i1 = s; }
        } else { d2 = d; i2 = s; }
    }
}

constexpr int IWARPS = 8;
constexpr int TPW    = 4;

__global__ void interp3nn(const float* __restrict__ src_xyz,
                          const float* __restrict__ tgt_xyz,
                          const float* __restrict__ feats,
                          float* __restrict__ out,
                          int NS, int NT) {
    extern __shared__ float4 sp[];

    const int b = blockIdx.y;
    const float* S = src_xyz + (size_t)b * NS * 3;
    for (int i = threadIdx.x; i < NS; i += blockDim.x) {
        float4 p;
        p.x = S[3 * i + 0];
        p.y = S[3 * i + 1];
        p.z = S[3 * i + 2];
        p.w = 0.f;
        sp[i] = p;
    }
    __syncthreads();

    const int warp = threadIdx.x >> 5;
    const int lane = threadIdx.x & 31;
    const int tbase = (blockIdx.x * IWARPS + warp) * TPW;
    if (tbase >= NT) return;

    float tx[TPW], ty[TPW], tz[TPW];
    float d0[TPW], d1[TPW], d2[TPW];
    int   i0[TPW], i1[TPW], i2[TPW];
#pragma unroll
    for (int j = 0; j < TPW; j++) {
        int t = min(tbase + j, NT - 1);
        const float* T = tgt_xyz + ((size_t)b * NT + t) * 3;
        tx[j] = T[0]; ty[j] = T[1]; tz[j] = T[2];
        d0[j] = d1[j] = d2[j] = 3.4e38f;
        i0[j] = i1[j] = i2[j] = 0;
    }

    for (int s = lane; s < NS; s += 32) {
        float4 p = sp[s];
#pragma unroll
        for (int j = 0; j < TPW; j++) {
            float dx = tx[j] - p.x, dy = ty[j] - p.y, dz = tz[j] - p.z;
            float d = dx * dx + dy * dy + dz * dz;
            ins3(d, s, d0[j], i0[j], d1[j], i1[j], d2[j], i2[j]);
        }
    }

#pragma unroll
    for (int j = 0; j < TPW; j++) {
#pragma unroll
        for (int off = 16; off > 0; off >>= 1) {
            float od0 = __shfl_xor_sync(0xffffffffu, d0[j], off);
            int   oi0 = __shfl_xor_sync(0xffffffffu, i0[j], off);
            float od1 = __shfl_xor_sync(0xffffffffu, d1[j], off);
            int   oi1 = __shfl_xor_sync(0xffffffffu, i1[j], off);
            float od2 = __shfl_xor_sync(0xffffffffu, d2[j], off);
            int   oi2 = __shfl_xor_sync(0xffffffffu, i2[j], off);
            ins3(od0, oi0, d0[j], i0[j], d1[j], i1[j], d2[j], i2[j]);
            ins3(od1, oi1, d0[j], i0[j], d1[j], i1[j], d2[j], i2[j]);
            ins3(od2, oi2, d0[j], i0[j], d1[j], i1[j], d2[j], i2[j]);
        }
    }

#pragma unroll
    for (int j = 0; j < TPW; j++) {
        int t = tbase + j;
        if (t >= NT) break;
        float s0 = sqrtf(fmaxf(d0[j], 0.f));
        float s1 = sqrtf(fmaxf(d1[j], 0.f));
        float s2 = sqrtf(fmaxf(d2[j], 0.f));
        float w0 = 1.f / (s0 + 1e-8f);
        float w1 = 1.f / (s1 + 1e-8f);
        float w2 = 1.f / (s2 + 1e-8f);
        float wi = 1.f / (w0 + w1 + w2);
        w0 *= wi; w1 *= wi; w2 *= wi;

        const float4* f0 = (const float4*)(feats + ((size_t)b * NS + i0[j]) * CCH);
        const float4* f1 = (const float4*)(feats + ((size_t)b * NS + i1[j]) * CCH);
        const float4* f2 = (const float4*)(feats + ((size_t)b * NS + i2[j]) * CCH);
        float4 a = f0[lane], bb = f1[lane], cc = f2[lane];
        float4 r;
        r.x = w0 * a.x + w1 * bb.x + w2 * cc.x;
        r.y = w0 * a.y + w1 * bb.y + w2 * cc.y;
        r.z = w0 * a.z + w1 * bb.z + w2 * cc.z;
        r.w = w0 * a.w + w1 * bb.w + w2 * cc.w;
        ((float4*)(out + ((size_t)b * NT + t) * CCH))[lane] = r;
    }
}

// ---------------------------------------------------------------------------
// mma.sync tf32 GEMM, cp.async double-buffered, register-side 3xTF32 split.
// C (rows x 128) = X (rows x KD) @ W^T.  CTA tile 128(M) x 64(N) x 32(K).
// 256 threads = 8 warps (4x2), warp tile 32x32.  grid = (rows/128, 2).
// ---------------------------------------------------------------------------
constexpr int SA = 36;   // padded smem row stride (words)
constexpr int SC = 68;   // epilogue stage stride
constexpr int A_WORDS = 128 * SA;   // 4608
constexpr int B_WORDS = 64 * SA;    // 2304
constexpr int OFF_SCL = 0;          // scale[128], shift[128]
constexpr int OFF_A   = 256;
constexpr int OFF_B   = OFF_A + 2 * A_WORDS;
constexpr int GEMM_SMEM = (OFF_B + 2 * B_WORDS) * 4;   // 56320 B

template <int KD, bool SPLIT, bool AFFINE, bool SUMS, bool BIAS>
__global__ __launch_bounds__(256) void gemm_mma(
        const float* __restrict__ A0, const float* __restrict__ A1,
        const float* __restrict__ W,
        const float* __restrict__ scale, const float* __restrict__ shift,
        const float* __restrict__ bias,
        float* __restrict__ Cout,
        float* __restrict__ psum, float* __restrict__ psq) {
    extern __shared__ float smf[];
    const uint32_t smb = smem_u32(smf);

    const int t    = threadIdx.x;
    const int lane = t & 31;
    const int warp = t >> 5;
    const int wm   = warp >> 1;
    const int wn   = warp & 1;
    const int g    = lane >> 2;
    const int tig  = lane & 3;
    const int blockRow = blockIdx.x * 128;
    const int oc0      = blockIdx.y * 64;

    if (AFFINE) {
        if (t < 128) {
            smf[OFF_SCL + t]       = scale[t];
            smf[OFF_SCL + 128 + t] = shift[t];
        }
    }

    // per-thread prefetch coordinates
    const int arow = t >> 3;            // 0..31 (x4 rows via i)
    const int acq  = (t & 7) * 4;       // col group

    auto prefetch = [&](int kc) {
        int buf = kc & 1;
        uint32_t abase = smb + (OFF_A + buf * A_WORDS) * 4;
#pragma unroll
        for (int i = 0; i < 4; i++) {
            int row = arow + i * 32;
            int kg  = kc * 32 + acq;
            const float* src;
            if (SPLIT) {
                src = (kg < 128) ? A0 + (size_t)(blockRow + row) * 128 + kg
                                 : A1 + (size_t)(blockRow + row) * 128 + (kg - 128);
            } else {
                src = A0 + (size_t)(blockRow + row) * KD + kg;
            }
            cp_async16(abase + (row * SA + acq) * 4, src);
        }
        uint32_t bbase = smb + (OFF_B + buf * B_WORDS) * 4;
#pragma unroll
        for (int i = 0; i < 2; i++) {
            int row = arow + i * 32;
            const float* src = W + (size_t)(oc0 + row) * KD + kc * 32 + acq;
            cp_async16(bbase + (row * SA + acq) * 4, src);
        }
        cp_commit();
    };

    float c[2][4][4];
#pragma unroll
    for (int am = 0; am < 2; am++)
#pragma unroll
        for (int bn = 0; bn < 4; bn++)
#pragma unroll
            for (int r = 0; r < 4; r++) c[am][bn][r] = 0.f;

    constexpr int CH = KD / 32;
    prefetch(0);

#pragma unroll
    for (int kc = 0; kc < CH; kc++) {
        __syncthreads();   // WAR: buffer (kc+1)&1 fully consumed in chunk kc-1
        if (kc + 1 < CH) {
            prefetch(kc + 1);
            cp_wait<1>();
        } else {
            cp_wait<0>();
        }
        __syncthreads();   // chunk kc visible to all warps

        const float* Ab = smf + OFF_A + (kc & 1) * A_WORDS;
        const float* Bb = smf + OFF_B + (kc & 1) * B_WORDS;

#pragma unroll
        for (int ks = 0; ks < 4; ks++) {
            const int k0 = ks * 8;
            float sc0 = 1.f, sh0 = 0.f, sc1 = 1.f, sh1 = 0.f;
            if (AFFINE) {
                int kg = kc * 32 + k0 + tig;
                sc0 = smf[OFF_SCL + kg];
                sh0 = smf[OFF_SCL + 128 + kg];
                sc1 = smf[OFF_SCL + kg + 4];
                sh1 = smf[OFF_SCL + 128 + kg + 4];
            }
            uint32_t ah[2][4], al[2][4];
#pragma unroll
            for (int am = 0; am < 2; am++) {
                int r = wm * 32 + am * 16 + g;
                float v0 = Ab[(r    ) * SA + k0 + tig];
                float v1 = Ab[(r + 8) * SA + k0 + tig];
                float v2 = Ab[(r    ) * SA + k0 + tig + 4];
                float v3 = Ab[(r + 8) * SA + k0 + tig + 4];
                if (AFFINE) {
                    v0 = fmaxf(v0 * sc0 + sh0, 0.f);
                    v1 = fmaxf(v1 * sc0 + sh0, 0.f);
                    v2 = fmaxf(v2 * sc1 + sh1, 0.f);
                    v3 = fmaxf(v3 * sc1 + sh1, 0.f);
                }
                ah[am][0] = tf32_rna(v0); al[am][0] = __float_as_uint(v0 - __uint_as_float(ah[am][0]));
                ah[am][1] = tf32_rna(v1); al[am][1] = __float_as_uint(v1 - __uint_as_float(ah[am][1]));
                ah[am][2] = tf32_rna(v2); al[am][2] = __float_as_uint(v2 - __uint_as_float(ah[am][2]));
                ah[am][3] = tf32_rna(v3); al[am][3] = __float_as_uint(v3 - __uint_as_float(ah[am][3]));
            }
            uint32_t bh[4][2], bl[4][2];
#pragma unroll
            for (int bn = 0; bn < 4; bn++) {
                int n = wn * 32 + bn * 8 + g;
                float w0 = Bb[n * SA + k0 + tig];
                float w1 = Bb[n * SA + k0 + tig + 4];
                bh[bn][0] = tf32_rna(w0); bl[bn][0] = __float_as_uint(w0 - __uint_as_float(bh[bn][0]));
                bh[bn][1] = tf32_rna(w1); bl[bn][1] = __float_as_uint(w1 - __uint_as_float(bh[bn][1]));
            }
#pragma unroll
            for (int am = 0; am < 2; am++)
#pragma unroll
                for (int bn = 0; bn < 4; bn++) {
                    mma_tf32(c[am][bn], ah[am], bh[bn]);
                    mma_tf32(c[am][bn], ah[am], bl[bn]);
                    mma_tf32(c[am][bn], al[am], bh[bn]);
                }
        }
    }

    // ---- epilogue: frags -> smem stage (pre-bias) ----
    __syncthreads();
    float* stage = smf;
#pragma unroll
    for (int am = 0; am < 2; am++) {
        int row0 = wm * 32 + am * 16 + g;
#pragma unroll
        for (int bn = 0; bn < 4; bn++) {
            int col = wn * 32 + bn * 8 + 2 * tig;
            stage[(row0    ) * SC + col    ] = c[am][bn][0];
            stage[(row0    ) * SC + col + 1] = c[am][bn][1];
            stage[(row0 + 8) * SC + col    ] = c[am][bn][2];
            stage[(row0 + 8) * SC + col + 1] = c[am][bn][3];
        }
    }
    __syncthreads();

    if (SUMS && t < 64) {
        float s = 0.f, q = 0.f;
#pragma unroll 8
        for (int r = 0; r < 128; r++) {
            float v = stage[r * SC + t];
            s += v; q += v * v;
        }
        psum[blockIdx.x * 128 + oc0 + t] = s;
        psq [blockIdx.x * 128 + oc0 + t] = q;
    }

#pragma unroll
    for (int i = 0; i < 8; i++) {
        int idx = t + i * 256;
        int row = idx >> 4;
        int cq  = (idx & 15) * 4;
        float4 v = *(float4*)&stage[row * SC + cq];
        if (BIAS) {
            v.x += bias[oc0 + cq + 0];
            v.y += bias[oc0 + cq + 1];
            v.z += bias[oc0 + cq + 2];
            v.w += bias[oc0 + cq + 3];
        }
        *(float4*)(Cout + (size_t)(blockRow + row) * 128 + oc0 + cq) = v;
    }
}

// ---------------------------------------------------------------------------
// BN finalize (parallel)
// ---------------------------------------------------------------------------
__global__ __launch_bounds__(1024) void bn_finalize(
        const float* __restrict__ psum, const float* __restrict__ psq,
        int nchunks, float invN,
        const float* __restrict__ g, const float* __restrict__ b,
        float* __restrict__ scale, float* __restrict__ shift) {
    __shared__ float ssum[8][128];
    __shared__ float ssq [8][128];
    const int c     = threadIdx.x & 127;
    const int slice = threadIdx.x >> 7;

    float s = 0.f, q = 0.f;
    for (int k = slice; k < nchunks; k += 8) {
        s += psum[k * 128 + c];
        q += psq [k * 128 + c];
    }
    ssum[slice][c] = s;
    ssq [slice][c] = q;
    __syncthreads();

    if (threadIdx.x < 128) {
        float ts = 0.f, tq = 0.f;
#pragma unroll
        for (int y = 0; y < 8; y++) { ts += ssum[y][c]; tq += ssq[y][c]; }
        float mu  = ts * invN;
        float var = fmaxf(tq * invN - mu * mu, 0.f);
        float sc  = g[c] * rsqrtf(var + 1e-5f);
        scale[c] = sc;
        shift[c] = b[c] - mu * sc;
    }
}

// ---------------------------------------------------------------------------
// Launch
// ---------------------------------------------------------------------------
extern "C" void kernel_launch(void* const* d_in, const int* in_sizes, int n_in,
                              void* d_out, int out_size) {
    const float* pts_r1 = (const float*)d_in[0];
    const float* pts_r2 = (const float*)d_in[1];
    const float* pts_r4 = (const float*)d_in[2];
    const float* feat0  = (const float*)d_in[3];
    const float* feat1  = (const float*)d_in[4];
    const float* feat2  = (const float*)d_in[5];
    const float* w3a = (const float*)d_in[6];
    const float* g3  = (const float*)d_in[7];
    const float* b3  = (const float*)d_in[8];
    const float* w3b = (const float*)d_in[9];
    const float* bb3 = (const float*)d_in[10];
    const float* w4a = (const float*)d_in[11];
    const float* g4  = (const float*)d_in[12];
    const float* b4  = (const float*)d_in[13];
    const float* w4b = (const float*)d_in[14];
    const float* bb4 = (const float*)d_in[15];

    const int B  = 2;
    const int N1 = in_sizes[0] / (3 * B);   // 8192
    const int N2 = in_sizes[1] / (3 * B);   // 4096
    const int N4 = in_sizes[2] / (3 * B);   // 2048

    float *f2i, *h3, *n3, *n3i, *h4, *psum, *psq, *scale, *shift;
    cudaGetSymbolAddress((void**)&f2i,   g_f2i);
    cudaGetSymbolAddress((void**)&h3,    g_h3);
    cudaGetSymbolAddress((void**)&n3,    g_n3);
    cudaGetSymbolAddress((void**)&n3i,   g_n3i);
    cudaGetSymbolAddress((void**)&h4,    g_h4);
    cudaGetSymbolAddress((void**)&psum,  g_psum);
    cudaGetSymbolAddress((void**)&psq,   g_psq);
    cudaGetSymbolAddress((void**)&scale, g_scale);
    cudaGetSymbolAddress((void**)&shift, g_shift);

    cudaFuncSetAttribute(interp3nn, cudaFuncAttributeMaxDynamicSharedMemorySize,
                         (int)(4096 * sizeof(float4)));
    cudaFuncSetAttribute(gemm_mma<256, true, false, true, false>,
                         cudaFuncAttributeMaxDynamicSharedMemorySize, GEMM_SMEM);
    cudaFuncSetAttribute(gemm_mma<128, false, true, false, true>,
                         cudaFuncAttributeMaxDynamicSharedMemorySize, GEMM_SMEM);

    // --- fnode 3: interp feat2 (r4 grid) onto r2 grid ---
    {
        dim3 grid((N2 + IWARPS * TPW - 1) / (IWARPS * TPW), B);
        size_t shmem = (size_t)N4 * sizeof(float4);
        interp3nn<<<grid, 256, shmem>>>(pts_r4, pts_r2, feat2, f2i, N4, N2);
    }
    gemm_mma<256, true, false, true, false>
        <<<dim3((B * N2) / 128, 2), 256, GEMM_SMEM>>>(
        feat1, f2i, w3a, nullptr, nullptr, nullptr, h3, psum, psq);
    bn_finalize<<<1, 1024>>>(psum, psq, (B * N2) / 128, 1.f / (B * N2), g3, b3, scale, shift);
    gemm_mma<128, false, true, false, true>
        <<<dim3((B * N2) / 128, 2), 256, GEMM_SMEM>>>(
        h3, nullptr, w3b, scale, shift, bb3, n3, nullptr, nullptr);

    // --- fnode 4: interp n3 (r2 grid) onto r1 grid ---
    {
        dim3 grid((N1 + IWARPS * TPW - 1) / (IWARPS * TPW), B);
        size_t shmem = (size_t)N2 * sizeof(float4);
        interp3nn<<<grid, 256, shmem>>>(pts_r2, pts_r1, n3, n3i, N2, N1);
    }
    gemm_mma<256, true, false, true, false>
        <<<dim3((B * N1) / 128, 2), 256, GEMM_SMEM>>>(
        feat0, n3i, w4a, nullptr, nullptr, nullptr, h4, psum, psq);
    bn_finalize<<<1, 1024>>>(psum, psq, (B * N1) / 128, 1.f / (B * N1), g4, b4, scale, shift);
    gemm_mma<128, false, true, false, true>
        <<<dim3((B * N1) / 128, 2), 256, GEMM_SMEM>>>(
        h4, nullptr, w4b, scale, shift, bb4, (float*)d_out, nullptr, nullptr);
}